// round 2
// baseline (speedup 1.0000x reference)
#include <cuda_runtime.h>
#include <math.h>

// Problem constants
#define BB   64
#define MM   2048
#define DD   256
#define KK   64
#define HH   512
#define XROW 257          // x row = 256 feats + 1 label
#define OUTD 512
#define INVM (1.0f/2048.0f)

// ---------------- scratch (device globals; no allocation) ----------------
__device__ float d_gpart[BB][16][HH];   // stage1 partials per row-tile
__device__ float d_lpart[BB][16];       // label-sum partials
__device__ float d_Lsum[BB];
__device__ float d_logits[BB][MM];      // logits + gumbel
__device__ float d_msg[BB][HH];
__device__ int   d_selIdx[BB][KK];
__device__ float d_selLab[BB];
__device__ float d_g2[BB][HH];

// ============================================================================
// Stage 1: big GEMM  r = relu(feats @ k1_w0 + b0), fused label-weighted
// row-reduction:  gpart[b][rt][c] = sum_{rows in tile} label[row]*r[row,c]
// Grid: (colTile=4, rowTile=16, b=64). Block 256 thr, 128x128 tile, 8x8 frag.
// ============================================================================
__global__ void __launch_bounds__(256) stage1_kernel(
    const float* __restrict__ x, const float* __restrict__ w0,
    const float* __restrict__ b0)
{
    const int ct = blockIdx.x;       // 0..3   (128 cols each)
    const int rt = blockIdx.y;       // 0..15  (128 rows each)
    const int b  = blockIdx.z;
    const int tid = threadIdx.x;
    const int tx = tid & 15;         // col group
    const int ty = tid >> 4;         // row group

    __shared__ float As[2][16][132]; // [kk][row], padded
    __shared__ float Bs[2][16][128]; // [kk][col]
    __shared__ float red[16][128];

    const float* __restrict__ xb  = x + ((size_t)b*MM + (size_t)rt*128) * XROW;
    const float* __restrict__ w0c = w0 + ct*128;

    float acc[8][8];
    #pragma unroll
    for (int i=0;i<8;i++)
        #pragma unroll
        for (int j=0;j<8;j++) acc[i][j]=0.f;

    // prologue loads (k0 = 0)
    #pragma unroll
    for (int t=0;t<8;t++){
        int idx = tid + t*256;
        int row = idx >> 4, kk = idx & 15;
        As[0][kk][row] = xb[(size_t)row*XROW + kk];
    }
    #pragma unroll
    for (int t=0;t<8;t++){
        int idx = tid + t*256;
        int kk = idx >> 7, col = idx & 127;
        Bs[0][kk][col] = w0c[(size_t)kk*HH + col];
    }
    __syncthreads();

    int buf = 0;
    for (int k0=0;k0<DD;k0+=16){
        if (k0 + 16 < DD){
            int kn = k0 + 16;
            #pragma unroll
            for (int t=0;t<8;t++){
                int idx = tid + t*256;
                int row = idx >> 4, kk = idx & 15;
                As[buf^1][kk][row] = xb[(size_t)row*XROW + kn + kk];
            }
            #pragma unroll
            for (int t=0;t<8;t++){
                int idx = tid + t*256;
                int kk = idx >> 7, col = idx & 127;
                Bs[buf^1][kk][col] = w0c[(size_t)(kn+kk)*HH + col];
            }
        }
        #pragma unroll
        for (int kk=0;kk<16;kk++){
            float a[8], bw[8];
            #pragma unroll
            for (int i=0;i<8;i++) a[i]  = As[buf][kk][ty*8+i];
            #pragma unroll
            for (int j=0;j<8;j++) bw[j] = Bs[buf][kk][tx*8+j];
            #pragma unroll
            for (int i=0;i<8;i++)
                #pragma unroll
                for (int j=0;j<8;j++) acc[i][j] += a[i]*bw[j];
        }
        __syncthreads();
        buf ^= 1;
    }

    // epilogue: bias + relu + label weight, reduce over the 8 rows of this frag
    float lab[8];
    #pragma unroll
    for (int i=0;i<8;i++)
        lab[i] = xb[(size_t)(ty*8+i)*XROW + DD];   // label column
    float gf[8];
    #pragma unroll
    for (int j=0;j<8;j++){
        float bias = b0[ct*128 + tx*8 + j];
        float s = 0.f;
        #pragma unroll
        for (int i=0;i<8;i++){
            float v = acc[i][j] + bias;
            v = v > 0.f ? v : 0.f;
            s += lab[i]*v;
        }
        gf[j] = s;
    }
    // reduce over the 16 ty groups (deterministic tree via smem)
    #pragma unroll
    for (int j=0;j<8;j++) red[ty][tx*8+j] = gf[j];
    __syncthreads();
    if (tid < 128){
        float s = 0.f;
        #pragma unroll
        for (int t=0;t<16;t++) s += red[t][tid];
        d_gpart[b][rt][ct*128 + tid] = s;
    }
    // label-sum partial, computed once per row-tile (colTile 0 only)
    if (ct == 0){
        __syncthreads();
        if (tx == 0){
            float s = 0.f;
            #pragma unroll
            for (int i=0;i<8;i++) s += lab[i];
            red[0][ty] = s;
        }
        __syncthreads();
        if (tid == 0){
            float s = 0.f;
            #pragma unroll
            for (int t=0;t<16;t++) s += red[0][t];
            d_lpart[b][rt] = s;
        }
    }
}

// ============================================================================
// Stage 2: reduce gpart -> g; xt = (g@k1_w1)/M + b1*Lsum/M; m1 MLP + skip;
// logits_full = xt2 @ l1_w + l1_b; add gumbel to first 2048; store msg.
// Grid: 64 blocks (batch), 512 threads (one output lane each).
// ============================================================================
__global__ void __launch_bounds__(512) stage2_kernel(
    const float* __restrict__ k1w1, const float* __restrict__ k1b1,
    const float* __restrict__ m1w0, const float* __restrict__ m1b0,
    const float* __restrict__ m1w1, const float* __restrict__ m1b1,
    const float* __restrict__ l1w,  const float* __restrict__ l1b,
    const float* __restrict__ u)
{
    const int b = blockIdx.x;
    const int j = threadIdx.x;
    __shared__ float s0[HH], s1[HH];
    __shared__ float sL;

    float g = 0.f;
    #pragma unroll
    for (int rt=0;rt<16;rt++) g += d_gpart[b][rt][j];
    s0[j] = g;
    if (j == 0){
        float L = 0.f;
        #pragma unroll
        for (int rt=0;rt<16;rt++) L += d_lpart[b][rt];
        sL = L;
        d_Lsum[b] = L;
    }
    __syncthreads();
    const float Ls = sL;

    // xt = (g @ k1_w1)/M + k1_b1 * Ls/M
    float acc = 0.f;
    #pragma unroll 4
    for (int k=0;k<HH;k++) acc += s0[k]*k1w1[k*HH + j];
    float xt = acc*INVM + k1b1[j]*(Ls*INVM);
    __syncthreads();
    s1[j] = xt;
    __syncthreads();

    // t = relu(xt @ m1_w0 + b0)
    acc = 0.f;
    #pragma unroll 4
    for (int k=0;k<HH;k++) acc += s1[k]*m1w0[k*HH + j];
    float t = fmaxf(acc + m1b0[j], 0.f);
    __syncthreads();
    s0[j] = t;
    __syncthreads();

    // x2 = t @ m1_w1 + b1 + skip
    acc = 0.f;
    #pragma unroll 4
    for (int k=0;k<HH;k++) acc += s0[k]*m1w1[k*HH + j];
    float x2 = acc + m1b1[j] + xt;
    __syncthreads();
    s1[j] = x2;
    __syncthreads();

    // logits_full (2560) = x2 @ l1_w + l1_b ; gumbel on [0,2048)
    for (int jj=j; jj<HH+MM; jj+=HH){
        float a2 = 0.f;
        #pragma unroll 4
        for (int k=0;k<HH;k++) a2 += s1[k]*l1w[(size_t)k*(HH+MM) + jj];
        a2 += l1b[jj];
        if (jj < MM){
            float uu = u[(size_t)b*MM + jj];
            a2 += -logf(-logf(uu));          // gumbel
            d_logits[b][jj] = a2;
        } else {
            d_msg[b][jj-MM] = a2;
        }
    }
}

// ============================================================================
// Stage 2b: per-batch top-K (K=64) by iterative argmax (tie -> lowest index,
// matching jax.lax.top_k). Also computes sum of labels over selected rows.
// ============================================================================
__global__ void __launch_bounds__(256) topk_kernel(const float* __restrict__ x)
{
    const int b = blockIdx.x;
    const int tid = threadIdx.x;
    __shared__ float v[MM];
    __shared__ float bv[256];
    __shared__ int   bi[256];

    for (int i=tid;i<MM;i+=256) v[i] = d_logits[b][i];
    __syncthreads();

    for (int sel=0; sel<KK; sel++){
        float best = -3.0e38f; int besti = MM;
        for (int i=tid;i<MM;i+=256){
            float val = v[i];
            if (val > best){ best = val; besti = i; }   // strict > keeps lowest idx
        }
        bv[tid] = best; bi[tid] = besti;
        __syncthreads();
        for (int s=128;s>0;s>>=1){
            if (tid < s){
                float o = bv[tid+s]; int oi = bi[tid+s];
                if (o > bv[tid] || (o == bv[tid] && oi < bi[tid])){
                    bv[tid] = o; bi[tid] = oi;
                }
            }
            __syncthreads();
        }
        int w = bi[0];
        if (tid == 0){
            d_selIdx[b][sel] = w;
            v[w] = -3.0e38f;
        }
        __syncthreads();
    }

    // label sum over selected rows
    float s = 0.f;
    if (tid < KK){
        int r = d_selIdx[b][tid];
        s = x[((size_t)b*MM + r)*XROW + DD];
    }
    bv[tid] = s;
    __syncthreads();
    for (int st=128; st>0; st>>=1){
        if (tid < st) bv[tid] += bv[tid+st];
        __syncthreads();
    }
    if (tid == 0) d_selLab[b] = bv[0];
}

// ============================================================================
// Stage 3: sparse branch. Per batch: gather the 64 selected feature rows in
// TWO passes of 32 rows (smem limit), GEMM (32 x 512, K=256) vs k2_w0 per
// pass, relu+bias, label-weighted row reduce, accumulate -> g2.
// Grid: 64 blocks, 256 threads. Smem: 33KB fs + 4KB red + 256B lab < 48KB.
// ============================================================================
__global__ void __launch_bounds__(256) stage3_kernel(
    const float* __restrict__ x, const float* __restrict__ w0,
    const float* __restrict__ b0)
{
    const int b = blockIdx.x;
    const int tid = threadIdx.x;
    __shared__ float fs[32][DD+2];     // padded to kill bank conflicts
    __shared__ float lab[KK];
    __shared__ float red[16][64];

    if (tid < KK)
        lab[tid] = x[((size_t)b*MM + d_selIdx[b][tid])*XROW + DD];

    float g2acc[8];
    #pragma unroll
    for (int c=0;c<8;c++) g2acc[c] = 0.f;

    const int tx = tid & 15;           // col group (4 cols)
    const int ty = tid >> 4;           // row group (2 rows per pass)

    for (int pass=0; pass<2; pass++){
        __syncthreads();               // fs/lab ready; fs safe to overwrite
        for (int t=tid; t<32*DD; t+=256){
            int i = t >> 8, k = t & 255;
            fs[i][k] = x[((size_t)b*MM + d_selIdx[b][pass*32+i])*XROW + k];
        }
        __syncthreads();

        const float l0 = lab[pass*32 + ty*2 + 0];
        const float l1 = lab[pass*32 + ty*2 + 1];

        for (int cc=0; cc<8; cc++){    // 8 column chunks of 64
            const int colbase = cc*64 + tx*4;
            float acc[2][4];
            #pragma unroll
            for (int i=0;i<2;i++)
                #pragma unroll
                for (int j=0;j<4;j++) acc[i][j]=0.f;

            #pragma unroll 4
            for (int k=0;k<DD;k++){
                float4 bw = *reinterpret_cast<const float4*>(&w0[(size_t)k*HH + colbase]);
                float bwv[4] = {bw.x, bw.y, bw.z, bw.w};
                float a0 = fs[ty*2+0][k];
                float a1 = fs[ty*2+1][k];
                #pragma unroll
                for (int j=0;j<4;j++){
                    acc[0][j] += a0*bwv[j];
                    acc[1][j] += a1*bwv[j];
                }
            }
            float gf[4];
            #pragma unroll
            for (int j=0;j<4;j++){
                float bias = b0[colbase + j];
                float v0 = acc[0][j] + bias; v0 = v0 > 0.f ? v0 : 0.f;
                float v1 = acc[1][j] + bias; v1 = v1 > 0.f ? v1 : 0.f;
                gf[j] = l0*v0 + l1*v1;
            }
            __syncthreads();           // protect red reuse across cc/pass
            #pragma unroll
            for (int j=0;j<4;j++) red[ty][tx*4+j] = gf[j];
            __syncthreads();
            if (tid < 64){
                float s = 0.f;
                #pragma unroll
                for (int t2=0;t2<16;t2++) s += red[t2][tid];
                g2acc[cc] += s;
            }
        }
    }
    if (tid < 64){
        #pragma unroll
        for (int cc=0;cc<8;cc++) d_g2[b][cc*64 + tid] = g2acc[cc];
    }
}

// ============================================================================
// Stage 4: xt2 = (g2' @ k2_w1 + k2_b1*Lsum)/M  where
//          g2'[k] = g2[k] + relu(k2_b0[k]) * (Lsum - selLab)   (unselected rows)
// z = [xt2, msg]; y = relu(relu(z@m2w0+b0)@m2w1+b1); out = (y+z)@l2w + l2b
// Grid: 64 blocks, 512 threads.
// ============================================================================
__global__ void __launch_bounds__(512) stage4_kernel(
    const float* __restrict__ k2w1, const float* __restrict__ k2b0,
    const float* __restrict__ k2b1,
    const float* __restrict__ m2w0, const float* __restrict__ m2b0,
    const float* __restrict__ m2w1, const float* __restrict__ m2b1,
    const float* __restrict__ l2w,  const float* __restrict__ l2b,
    float* __restrict__ out)
{
    const int b = blockIdx.x;
    const int j = threadIdx.x;
    __shared__ float g2s[HH];
    __shared__ float zs[2*HH];
    __shared__ float t1[HH];

    const float Ls = d_Lsum[b];
    const float un = Ls - d_selLab[b];
    g2s[j] = d_g2[b][j] + fmaxf(k2b0[j], 0.f)*un;
    __syncthreads();

    float acc = 0.f;
    #pragma unroll 4
    for (int k=0;k<HH;k++) acc += g2s[k]*k2w1[k*HH + j];
    float xt2 = (acc + k2b1[j]*Ls)*INVM;

    zs[j]      = xt2;
    zs[HH + j] = d_msg[b][j];
    __syncthreads();

    acc = 0.f;
    #pragma unroll 4
    for (int k=0;k<2*HH;k++) acc += zs[k]*m2w0[(size_t)k*HH + j];
    t1[j] = fmaxf(acc + m2b0[j], 0.f);
    __syncthreads();

    float y0 = 0.f, y1 = 0.f;
    #pragma unroll 4
    for (int k=0;k<HH;k++){
        float t = t1[k];
        y0 += t*m2w1[(size_t)k*(2*HH) + j];
        y1 += t*m2w1[(size_t)k*(2*HH) + j + HH];
    }
    y0 = fmaxf(y0 + m2b1[j],      0.f) + zs[j];
    y1 = fmaxf(y1 + m2b1[j + HH], 0.f) + zs[HH + j];
    __syncthreads();                 // all zs reads done before overwrite
    zs[j]      = y0;
    zs[HH + j] = y1;
    __syncthreads();

    acc = 0.f;
    #pragma unroll 4
    for (int k=0;k<2*HH;k++) acc += zs[k]*l2w[(size_t)k*OUTD + j];
    out[(size_t)b*OUTD + j] = acc + l2b[j];
}

// ============================================================================
extern "C" void kernel_launch(void* const* d_in, const int* in_sizes, int n_in,
                              void* d_out, int out_size)
{
    const float* x     = (const float*)d_in[0];
    const float* u     = (const float*)d_in[1];
    const float* k1w0  = (const float*)d_in[2];
    const float* k1b0  = (const float*)d_in[3];
    const float* k1w1  = (const float*)d_in[4];
    const float* k1b1  = (const float*)d_in[5];
    const float* k2w0  = (const float*)d_in[6];
    const float* k2b0  = (const float*)d_in[7];
    const float* k2w1  = (const float*)d_in[8];
    const float* k2b1  = (const float*)d_in[9];
    const float* m1w0  = (const float*)d_in[10];
    const float* m1b0  = (const float*)d_in[11];
    const float* m1w1  = (const float*)d_in[12];
    const float* m1b1  = (const float*)d_in[13];
    const float* m2w0  = (const float*)d_in[14];
    const float* m2b0  = (const float*)d_in[15];
    const float* m2w1  = (const float*)d_in[16];
    const float* m2b1  = (const float*)d_in[17];
    const float* l1w   = (const float*)d_in[18];
    const float* l1b   = (const float*)d_in[19];
    const float* l2w   = (const float*)d_in[20];
    const float* l2b   = (const float*)d_in[21];
    float* out = (float*)d_out;

    dim3 g1(4, 16, BB);
    stage1_kernel<<<g1, 256>>>(x, k1w0, k1b0);
    stage2_kernel<<<BB, 512>>>(k1w1, k1b1, m1w0, m1b0, m1w1, m1b1, l1w, l1b, u);
    topk_kernel<<<BB, 256>>>(x);
    stage3_kernel<<<BB, 256>>>(x, k2w0, k2b0);
    stage4_kernel<<<BB, 512>>>(k2w1, k2b0, k2b1, m2w0, m2b0, m2w1, m2b1,
                               l2w, l2b, out);
}

// round 3
// speedup vs baseline: 1.3079x; 1.3079x over previous
#include <cuda_runtime.h>
#include <math.h>

// Problem constants
#define BB   64
#define MM   2048
#define DD   256
#define KK   64
#define HH   512
#define XROW 257          // x row = 256 feats + 1 label
#define OUTD 512
#define INVM (1.0f/2048.0f)

// ---------------- scratch (device globals; no allocation) ----------------
__device__ float d_gpart[BB][16][HH];   // stage1 partials per row-tile
__device__ float d_lpart[BB][16];       // label-sum partials
__device__ float d_Lsum[BB];
__device__ float d_logits[BB][MM];      // logits + gumbel
__device__ float d_msg[BB][HH];
__device__ int   d_selIdx[BB][KK];
__device__ float d_selLab[BB];
__device__ float d_g2[BB][HH];

// ============================================================================
// Stage 1: big GEMM  r = relu(feats @ k1_w0 + b0), fused label-weighted
// row-reduction:  gpart[b][rt][c] = sum_{rows in tile} label[row]*r[row,c]
// Grid: (colTile=4, rowTile=16, b=64). Block 256 thr, 128x128 tile, 8x8 frag.
// ============================================================================
__global__ void __launch_bounds__(256) stage1_kernel(
    const float* __restrict__ x, const float* __restrict__ w0,
    const float* __restrict__ b0)
{
    const int ct = blockIdx.x;       // 0..3   (128 cols each)
    const int rt = blockIdx.y;       // 0..15  (128 rows each)
    const int b  = blockIdx.z;
    const int tid = threadIdx.x;
    const int tx = tid & 15;         // col group
    const int ty = tid >> 4;         // row group

    __shared__ float As[2][16][132]; // [kk][row], padded
    __shared__ float Bs[2][16][128]; // [kk][col]
    __shared__ float red[16][128];

    const float* __restrict__ xb  = x + ((size_t)b*MM + (size_t)rt*128) * XROW;
    const float* __restrict__ w0c = w0 + ct*128;

    float acc[8][8];
    #pragma unroll
    for (int i=0;i<8;i++)
        #pragma unroll
        for (int j=0;j<8;j++) acc[i][j]=0.f;

    // prologue loads (k0 = 0)
    #pragma unroll
    for (int t=0;t<8;t++){
        int idx = tid + t*256;
        int row = idx >> 4, kk = idx & 15;
        As[0][kk][row] = xb[(size_t)row*XROW + kk];
    }
    #pragma unroll
    for (int t=0;t<2;t++){
        int idx = tid + t*256;               // 512 float4 loads total
        int kk = idx >> 5, colq = idx & 31;
        float4 v = *reinterpret_cast<const float4*>(&w0c[(size_t)kk*HH + colq*4]);
        *reinterpret_cast<float4*>(&Bs[0][kk][colq*4]) = v;
    }
    __syncthreads();

    int buf = 0;
    for (int k0=0;k0<DD;k0+=16){
        if (k0 + 16 < DD){
            int kn = k0 + 16;
            #pragma unroll
            for (int t=0;t<8;t++){
                int idx = tid + t*256;
                int row = idx >> 4, kk = idx & 15;
                As[buf^1][kk][row] = xb[(size_t)row*XROW + kn + kk];
            }
            #pragma unroll
            for (int t=0;t<2;t++){
                int idx = tid + t*256;
                int kk = idx >> 5, colq = idx & 31;
                float4 v = *reinterpret_cast<const float4*>(&w0c[(size_t)(kn+kk)*HH + colq*4]);
                *reinterpret_cast<float4*>(&Bs[buf^1][kk][colq*4]) = v;
            }
        }
        #pragma unroll
        for (int kk=0;kk<16;kk++){
            float a[8], bw[8];
            #pragma unroll
            for (int i=0;i<8;i++) a[i]  = As[buf][kk][ty*8+i];
            #pragma unroll
            for (int j=0;j<8;j++) bw[j] = Bs[buf][kk][tx*8+j];
            #pragma unroll
            for (int i=0;i<8;i++)
                #pragma unroll
                for (int j=0;j<8;j++) acc[i][j] += a[i]*bw[j];
        }
        __syncthreads();
        buf ^= 1;
    }

    // epilogue: bias + relu + label weight, reduce over the 8 rows of this frag
    float lab[8];
    #pragma unroll
    for (int i=0;i<8;i++)
        lab[i] = xb[(size_t)(ty*8+i)*XROW + DD];   // label column
    float gf[8];
    #pragma unroll
    for (int j=0;j<8;j++){
        float bias = b0[ct*128 + tx*8 + j];
        float s = 0.f;
        #pragma unroll
        for (int i=0;i<8;i++){
            float v = acc[i][j] + bias;
            v = v > 0.f ? v : 0.f;
            s += lab[i]*v;
        }
        gf[j] = s;
    }
    // reduce over the 16 ty groups (deterministic tree via smem)
    #pragma unroll
    for (int j=0;j<8;j++) red[ty][tx*8+j] = gf[j];
    __syncthreads();
    if (tid < 128){
        float s = 0.f;
        #pragma unroll
        for (int t=0;t<16;t++) s += red[t][tid];
        d_gpart[b][rt][ct*128 + tid] = s;
    }
    // label-sum partial, computed once per row-tile (colTile 0 only)
    if (ct == 0){
        __syncthreads();
        if (tx == 0){
            float s = 0.f;
            #pragma unroll
            for (int i=0;i<8;i++) s += lab[i];
            red[0][ty] = s;
        }
        __syncthreads();
        if (tid == 0){
            float s = 0.f;
            #pragma unroll
            for (int t=0;t<16;t++) s += red[0][t];
            d_lpart[b][rt] = s;
        }
    }
}

// ============================================================================
// Stage 2: reduce gpart -> g; xt = (g@k1_w1)/M + b1*Lsum/M; m1 MLP + skip;
// logits_full = xt2 @ l1_w + l1_b; add gumbel to first 2048; store msg.
// Grid: 64 blocks (batch), 512 threads (one output lane each).
// ============================================================================
__global__ void __launch_bounds__(512) stage2_kernel(
    const float* __restrict__ k1w1, const float* __restrict__ k1b1,
    const float* __restrict__ m1w0, const float* __restrict__ m1b0,
    const float* __restrict__ m1w1, const float* __restrict__ m1b1,
    const float* __restrict__ l1w,  const float* __restrict__ l1b,
    const float* __restrict__ u)
{
    const int b = blockIdx.x;
    const int j = threadIdx.x;
    __shared__ float s0[HH], s1[HH];
    __shared__ float sL;

    float g = 0.f;
    #pragma unroll
    for (int rt=0;rt<16;rt++) g += d_gpart[b][rt][j];
    s0[j] = g;
    if (j == 0){
        float L = 0.f;
        #pragma unroll
        for (int rt=0;rt<16;rt++) L += d_lpart[b][rt];
        sL = L;
        d_Lsum[b] = L;
    }
    __syncthreads();
    const float Ls = sL;

    // xt = (g @ k1_w1)/M + k1_b1 * Ls/M
    float acc = 0.f;
    #pragma unroll 4
    for (int k=0;k<HH;k++) acc += s0[k]*k1w1[k*HH + j];
    float xt = acc*INVM + k1b1[j]*(Ls*INVM);
    __syncthreads();
    s1[j] = xt;
    __syncthreads();

    // t = relu(xt @ m1_w0 + b0)
    acc = 0.f;
    #pragma unroll 4
    for (int k=0;k<HH;k++) acc += s1[k]*m1w0[k*HH + j];
    float t = fmaxf(acc + m1b0[j], 0.f);
    __syncthreads();
    s0[j] = t;
    __syncthreads();

    // x2 = t @ m1_w1 + b1 + skip
    acc = 0.f;
    #pragma unroll 4
    for (int k=0;k<HH;k++) acc += s0[k]*m1w1[k*HH + j];
    float x2 = acc + m1b1[j] + xt;
    __syncthreads();
    s1[j] = x2;
    __syncthreads();

    // logits_full (2560) = x2 @ l1_w + l1_b ; gumbel on [0,2048)
    for (int jj=j; jj<HH+MM; jj+=HH){
        float a2 = 0.f;
        #pragma unroll 4
        for (int k=0;k<HH;k++) a2 += s1[k]*l1w[(size_t)k*(HH+MM) + jj];
        a2 += l1b[jj];
        if (jj < MM){
            float uu = u[(size_t)b*MM + jj];
            a2 += -logf(-logf(uu));          // gumbel
            d_logits[b][jj] = a2;
        } else {
            d_msg[b][jj-MM] = a2;
        }
    }
}

// ============================================================================
// Stage 2b: per-batch top-K (K=64) by iterative argmax (tie -> lowest index,
// matching jax.lax.top_k). Also computes sum of labels over selected rows.
// ============================================================================
__global__ void __launch_bounds__(256) topk_kernel(const float* __restrict__ x)
{
    const int b = blockIdx.x;
    const int tid = threadIdx.x;
    __shared__ float v[MM];
    __shared__ float bv[256];
    __shared__ int   bi[256];

    for (int i=tid;i<MM;i+=256) v[i] = d_logits[b][i];
    __syncthreads();

    for (int sel=0; sel<KK; sel++){
        float best = -3.0e38f; int besti = MM;
        for (int i=tid;i<MM;i+=256){
            float val = v[i];
            if (val > best){ best = val; besti = i; }   // strict > keeps lowest idx
        }
        bv[tid] = best; bi[tid] = besti;
        __syncthreads();
        for (int s=128;s>0;s>>=1){
            if (tid < s){
                float o = bv[tid+s]; int oi = bi[tid+s];
                if (o > bv[tid] || (o == bv[tid] && oi < bi[tid])){
                    bv[tid] = o; bi[tid] = oi;
                }
            }
            __syncthreads();
        }
        int w = bi[0];
        if (tid == 0){
            d_selIdx[b][sel] = w;
            v[w] = -3.0e38f;
        }
        __syncthreads();
    }

    // label sum over selected rows
    float s = 0.f;
    if (tid < KK){
        int r = d_selIdx[b][tid];
        s = x[((size_t)b*MM + r)*XROW + DD];
    }
    bv[tid] = s;
    __syncthreads();
    for (int st=128; st>0; st>>=1){
        if (tid < st) bv[tid] += bv[tid+st];
        __syncthreads();
    }
    if (tid == 0) d_selLab[b] = bv[0];
}

// ============================================================================
// Stage 3 (rewritten): gathered tiled GEMM.
// Grid: (colTile=4, b=64) = 256 blocks. Each block: 64 gathered rows x 128
// cols, K=256, double-buffered smem for gathered features AND w0 tiles.
// Epilogue: bias+relu+label-weight, deterministic reduce -> d_g2[b][cols].
// Block 256 thr: tx=16 col groups (8 cols), ty=16 row groups (4 rows).
// ============================================================================
__global__ void __launch_bounds__(256) stage3_kernel(
    const float* __restrict__ x, const float* __restrict__ w0,
    const float* __restrict__ b0)
{
    const int ct = blockIdx.x;       // 0..3  (128 cols each)
    const int b  = blockIdx.y;
    const int tid = threadIdx.x;
    const int tx = tid & 15;         // col group (8 cols)
    const int ty = tid >> 4;         // row group (4 rows)

    __shared__ float As[2][16][68];  // [kk][row 0..63], padded
    __shared__ float Bs[2][16][128]; // [kk][col]
    __shared__ float red[16][128];
    __shared__ int   sidx[KK];
    __shared__ float lab[KK];

    if (tid < KK){
        int r = d_selIdx[b][tid];
        sidx[tid] = r;
        lab[tid] = x[((size_t)b*MM + r)*XROW + DD];
    }
    __syncthreads();

    const float* __restrict__ xb  = x + (size_t)b*MM*XROW;
    const float* __restrict__ w0c = w0 + ct*128;

    float acc[4][8];
    #pragma unroll
    for (int i=0;i<4;i++)
        #pragma unroll
        for (int j=0;j<8;j++) acc[i][j]=0.f;

    // prologue (k0 = 0)
    #pragma unroll
    for (int t=0;t<4;t++){
        int idx = tid + t*256;               // 1024 = 16kk x 64row
        int row = idx >> 4, kk = idx & 15;
        As[0][kk][row] = xb[(size_t)sidx[row]*XROW + kk];
    }
    #pragma unroll
    for (int t=0;t<2;t++){
        int idx = tid + t*256;               // 512 float4 = 16kk x 128col
        int kk = idx >> 5, colq = idx & 31;
        float4 v = *reinterpret_cast<const float4*>(&w0c[(size_t)kk*HH + colq*4]);
        *reinterpret_cast<float4*>(&Bs[0][kk][colq*4]) = v;
    }
    __syncthreads();

    int buf = 0;
    for (int k0=0;k0<DD;k0+=16){
        if (k0 + 16 < DD){
            int kn = k0 + 16;
            #pragma unroll
            for (int t=0;t<4;t++){
                int idx = tid + t*256;
                int row = idx >> 4, kk = idx & 15;
                As[buf^1][kk][row] = xb[(size_t)sidx[row]*XROW + kn + kk];
            }
            #pragma unroll
            for (int t=0;t<2;t++){
                int idx = tid + t*256;
                int kk = idx >> 5, colq = idx & 31;
                float4 v = *reinterpret_cast<const float4*>(&w0c[(size_t)(kn+kk)*HH + colq*4]);
                *reinterpret_cast<float4*>(&Bs[buf^1][kk][colq*4]) = v;
            }
        }
        #pragma unroll
        for (int kk=0;kk<16;kk++){
            float a[4], bw[8];
            #pragma unroll
            for (int i=0;i<4;i++) a[i]  = As[buf][kk][ty*4+i];
            #pragma unroll
            for (int j=0;j<8;j++) bw[j] = Bs[buf][kk][tx*8+j];
            #pragma unroll
            for (int i=0;i<4;i++)
                #pragma unroll
                for (int j=0;j<8;j++) acc[i][j] += a[i]*bw[j];
        }
        __syncthreads();
        buf ^= 1;
    }

    // epilogue: bias + relu + label weight; reduce over rows
    float lf[4];
    #pragma unroll
    for (int i=0;i<4;i++) lf[i] = lab[ty*4+i];
    float gf[8];
    #pragma unroll
    for (int j=0;j<8;j++){
        float bias = b0[ct*128 + tx*8 + j];
        float s = 0.f;
        #pragma unroll
        for (int i=0;i<4;i++){
            float v = acc[i][j] + bias;
            v = v > 0.f ? v : 0.f;
            s += lf[i]*v;
        }
        gf[j] = s;
    }
    #pragma unroll
    for (int j=0;j<8;j++) red[ty][tx*8+j] = gf[j];
    __syncthreads();
    if (tid < 128){
        float s = 0.f;
        #pragma unroll
        for (int t=0;t<16;t++) s += red[t][tid];
        d_g2[b][ct*128 + tid] = s;
    }
}

// ============================================================================
// Stage 4: xt2 = (g2' @ k2_w1 + k2_b1*Lsum)/M  where
//          g2'[k] = g2[k] + relu(k2_b0[k]) * (Lsum - selLab)   (unselected rows)
// z = [xt2, msg]; y = relu(relu(z@m2w0+b0)@m2w1+b1); out = (y+z)@l2w + l2b
// Grid: 64 blocks, 512 threads.
// ============================================================================
__global__ void __launch_bounds__(512) stage4_kernel(
    const float* __restrict__ k2w1, const float* __restrict__ k2b0,
    const float* __restrict__ k2b1,
    const float* __restrict__ m2w0, const float* __restrict__ m2b0,
    const float* __restrict__ m2w1, const float* __restrict__ m2b1,
    const float* __restrict__ l2w,  const float* __restrict__ l2b,
    float* __restrict__ out)
{
    const int b = blockIdx.x;
    const int j = threadIdx.x;
    __shared__ float g2s[HH];
    __shared__ float zs[2*HH];
    __shared__ float t1[HH];

    const float Ls = d_Lsum[b];
    const float un = Ls - d_selLab[b];
    g2s[j] = d_g2[b][j] + fmaxf(k2b0[j], 0.f)*un;
    __syncthreads();

    float acc = 0.f;
    #pragma unroll 4
    for (int k=0;k<HH;k++) acc += g2s[k]*k2w1[k*HH + j];
    float xt2 = (acc + k2b1[j]*Ls)*INVM;

    zs[j]      = xt2;
    zs[HH + j] = d_msg[b][j];
    __syncthreads();

    acc = 0.f;
    #pragma unroll 4
    for (int k=0;k<2*HH;k++) acc += zs[k]*m2w0[(size_t)k*HH + j];
    t1[j] = fmaxf(acc + m2b0[j], 0.f);
    __syncthreads();

    float y0 = 0.f, y1 = 0.f;
    #pragma unroll 4
    for (int k=0;k<HH;k++){
        float t = t1[k];
        y0 += t*m2w1[(size_t)k*(2*HH) + j];
        y1 += t*m2w1[(size_t)k*(2*HH) + j + HH];
    }
    y0 = fmaxf(y0 + m2b1[j],      0.f) + zs[j];
    y1 = fmaxf(y1 + m2b1[j + HH], 0.f) + zs[HH + j];
    __syncthreads();                 // all zs reads done before overwrite
    zs[j]      = y0;
    zs[HH + j] = y1;
    __syncthreads();

    acc = 0.f;
    #pragma unroll 4
    for (int k=0;k<2*HH;k++) acc += zs[k]*l2w[(size_t)k*OUTD + j];
    out[(size_t)b*OUTD + j] = acc + l2b[j];
}

// ============================================================================
extern "C" void kernel_launch(void* const* d_in, const int* in_sizes, int n_in,
                              void* d_out, int out_size)
{
    const float* x     = (const float*)d_in[0];
    const float* u     = (const float*)d_in[1];
    const float* k1w0  = (const float*)d_in[2];
    const float* k1b0  = (const float*)d_in[3];
    const float* k1w1  = (const float*)d_in[4];
    const float* k1b1  = (const float*)d_in[5];
    const float* k2w0  = (const float*)d_in[6];
    const float* k2b0  = (const float*)d_in[7];
    const float* k2w1  = (const float*)d_in[8];
    const float* k2b1  = (const float*)d_in[9];
    const float* m1w0  = (const float*)d_in[10];
    const float* m1b0  = (const float*)d_in[11];
    const float* m1w1  = (const float*)d_in[12];
    const float* m1b1  = (const float*)d_in[13];
    const float* m2w0  = (const float*)d_in[14];
    const float* m2b0  = (const float*)d_in[15];
    const float* m2w1  = (const float*)d_in[16];
    const float* m2b1  = (const float*)d_in[17];
    const float* l1w   = (const float*)d_in[18];
    const float* l1b   = (const float*)d_in[19];
    const float* l2w   = (const float*)d_in[20];
    const float* l2b   = (const float*)d_in[21];
    float* out = (float*)d_out;

    dim3 g1(4, 16, BB);
    stage1_kernel<<<g1, 256>>>(x, k1w0, k1b0);
    stage2_kernel<<<BB, 512>>>(k1w1, k1b1, m1w0, m1b0, m1w1, m1b1, l1w, l1b, u);
    topk_kernel<<<BB, 256>>>(x);
    dim3 g3(4, BB);
    stage3_kernel<<<g3, 256>>>(x, k2w0, k2b0);
    stage4_kernel<<<BB, 512>>>(k2w1, k2b0, k2b1, m2w0, m2b0, m2w1, m2b1,
                               l2w, l2b, out);
}

// round 5
// speedup vs baseline: 1.7336x; 1.3255x over previous
#include <cuda_runtime.h>
#include <cuda_bf16.h>
#include <math.h>
#include <stdint.h>

// Problem constants
#define BB   64
#define MM   2048
#define DD   256
#define KK   64
#define HH   512
#define XROW 257          // x row = 256 feats + 1 label
#define OUTD 512
#define INVM (1.0f/2048.0f)

// ---------------- scratch (device globals; no allocation) ----------------
__device__ float d_gpart[BB][16][HH];   // stage1 partials per row-tile
__device__ float d_lpart[BB][16];       // label-sum partials
__device__ float d_Lsum[BB];
__device__ float d_logits[BB][MM];      // logits + gumbel
__device__ float d_msg[BB][HH];
__device__ int   d_selIdx[BB][KK];
__device__ float d_selLab[BB];
__device__ float d_g2[BB][HH];
// k1_w0 transposed to [n][k] bf16 hi/lo for ldmatrix-friendly B tiles
__device__ __nv_bfloat16 d_bthi[HH*DD];
__device__ __nv_bfloat16 d_btlo[HH*DD];

// ---------------- mma.sync helpers ----------------
#define LDSM4(R, addr) \
  asm volatile("ldmatrix.sync.aligned.m8n8.x4.shared.b16 {%0,%1,%2,%3}, [%4];" \
    : "=r"((R)[0]), "=r"((R)[1]), "=r"((R)[2]), "=r"((R)[3]) : "r"(addr))

#define MMA16816(C, A, B0v, B1v) \
  asm volatile("mma.sync.aligned.m16n8k16.row.col.f32.bf16.bf16.f32 " \
    "{%0,%1,%2,%3}, {%4,%5,%6,%7}, {%8,%9}, {%0,%1,%2,%3};" \
    : "+f"((C)[0]), "+f"((C)[1]), "+f"((C)[2]), "+f"((C)[3]) \
    : "r"((A)[0]), "r"((A)[1]), "r"((A)[2]), "r"((A)[3]), "r"(B0v), "r"(B1v))

__device__ __forceinline__ uint32_t smem_addr(const void* p){
    return (uint32_t)__cvta_generic_to_shared(p);
}

// ============================================================================
// Prep: transpose k1_w0 (fp32 [k=256][n=512]) -> bf16 hi/lo [n=512][k=256]
// ============================================================================
__global__ void __launch_bounds__(512) prep_w0_kernel(const float* __restrict__ w0)
{
    int id = blockIdx.x*512 + threadIdx.x;   // 0..131071
    int k  = id >> 9;                        // 0..255
    int n  = id & 511;                       // 0..511
    float v = w0[(size_t)k*HH + n];
    __nv_bfloat16 h = __float2bfloat16(v);
    __nv_bfloat16 l = __float2bfloat16(v - __bfloat162float(h));
    d_bthi[(size_t)n*DD + k] = h;
    d_btlo[(size_t)n*DD + k] = l;
}

// ============================================================================
// Stage 1 (mma.sync bf16 3-term split): per CTA computes
//   D[128 rows][128 cols] = feats(128x256) @ k1_w0[:, ct*128:+128]
// with fp32 accum via hi*hi + hi*lo + lo*hi, then fused bias+relu+
// label-weight epilogue reduced over rows -> d_gpart[b][rt][cols].
// Grid: (ct=4, rt=16, b=64) = 4096 CTAs, 256 threads (8 warps, 2x4 grid,
// warp tile 64x32). K chunks of 32 (2 k-steps of 16), single buffer.
// ============================================================================
__global__ void __launch_bounds__(256) stage1_mma_kernel(
    const float* __restrict__ x, const float* __restrict__ b0)
{
    const int ct = blockIdx.x;   // 0..3
    const int rt = blockIdx.y;   // 0..15
    const int b  = blockIdx.z;
    const int tid  = threadIdx.x;
    const int lane = tid & 31, wid = tid >> 5;
    const int warpRow = wid & 1;      // 2 row strips of 64
    const int warpCol = wid >> 1;     // 4 col strips of 32

    __shared__ __nv_bfloat16 Ah[128][40], Al[128][40];
    __shared__ __nv_bfloat16 Bh[128][40], Bl[128][40];
    __shared__ float lab_s[128];
    __shared__ float red2[2][128];

    const float* __restrict__ xb = x + (size_t)(b*MM + rt*128)*XROW;
    if (tid < 128) lab_s[tid] = xb[(size_t)tid*XROW + DD];

    float acc[4][4][4];               // [mf][nf][c]
    #pragma unroll
    for (int i=0;i<4;i++)
        #pragma unroll
        for (int j=0;j<4;j++)
            #pragma unroll
            for (int c=0;c<4;c++) acc[i][j][c] = 0.f;

    const __nv_bfloat16* __restrict__ bth = d_bthi + (size_t)(ct*128)*DD;
    const __nv_bfloat16* __restrict__ btl = d_btlo + (size_t)(ct*128)*DD;

    for (int kc = 0; kc < 8; kc++){
        __syncthreads();              // prior fragments consumed
        // ---- A: load fp32, convert to bf16 hi/lo ----
        {
            const int k = lane;       // 0..31
            #pragma unroll
            for (int it = 0; it < 16; it++){
                int row = (tid >> 5) + it*8;
                float v = xb[(size_t)row*XROW + kc*32 + k];
                __nv_bfloat16 h = __float2bfloat16(v);
                Ah[row][k] = h;
                Al[row][k] = __float2bfloat16(v - __bfloat162float(h));
            }
        }
        // ---- B: copy pre-transposed bf16 hi/lo rows (n-major) ----
        {
            int n  = tid >> 1;
            int j0 = (tid & 1)*2;
            const uint4* sh = reinterpret_cast<const uint4*>(bth + (size_t)n*DD + kc*32);
            const uint4* sl = reinterpret_cast<const uint4*>(btl + (size_t)n*DD + kc*32);
            uint4* dh = reinterpret_cast<uint4*>(&Bh[n][0]);
            uint4* dl = reinterpret_cast<uint4*>(&Bl[n][0]);
            dh[j0]   = sh[j0];
            dh[j0+1] = sh[j0+1];
            dl[j0]   = sl[j0];
            dl[j0+1] = sl[j0+1];
        }
        __syncthreads();

        #pragma unroll
        for (int ks = 0; ks < 2; ks++){
            uint32_t ah[4][4], al[4][4], bh[2][4], bl[2][4];
            const int arow = warpRow*64 + (lane & 15);
            const int acol = ks*16 + (lane >> 4)*8;
            #pragma unroll
            for (int mf = 0; mf < 4; mf++){
                LDSM4(ah[mf], smem_addr(&Ah[arow + mf*16][acol]));
                LDSM4(al[mf], smem_addr(&Al[arow + mf*16][acol]));
            }
            const int brow = warpCol*32 + (lane & 15);
            #pragma unroll
            for (int np = 0; np < 2; np++){
                LDSM4(bh[np], smem_addr(&Bh[brow + np*16][acol]));
                LDSM4(bl[np], smem_addr(&Bl[brow + np*16][acol]));
            }
            #pragma unroll
            for (int mf = 0; mf < 4; mf++){
                #pragma unroll
                for (int nf = 0; nf < 4; nf++){
                    const int np = nf >> 1, odd = nf & 1;
                    uint32_t b0h = bh[np][odd], b1h = bh[np][odd+2];
                    uint32_t b0l = bl[np][odd], b1l = bl[np][odd+2];
                    MMA16816(acc[mf][nf], ah[mf], b0h, b1h);
                    MMA16816(acc[mf][nf], ah[mf], b0l, b1l);
                    MMA16816(acc[mf][nf], al[mf], b0h, b1h);
                }
            }
        }
    }

    // ---- epilogue: bias + relu + label weight, reduce over 128 rows ----
    // thread owns (row0 = warpRow*64 + mf*16 + lane>>2, row1 = row0+8),
    // cols = warpCol*32 + nf*8 + (lane&3)*2 + {0,1}
    {
        const int r0 = warpRow*64 + (lane >> 2);
        float cs[4][2];
        #pragma unroll
        for (int nf = 0; nf < 4; nf++){
            const int colg = ct*128 + warpCol*32 + nf*8 + (lane & 3)*2;
            float bias0 = __ldg(&b0[colg]);
            float bias1 = __ldg(&b0[colg+1]);
            float s0 = 0.f, s1 = 0.f;
            #pragma unroll
            for (int mf = 0; mf < 4; mf++){
                float la = lab_s[r0 + mf*16];
                float lb = lab_s[r0 + mf*16 + 8];
                float v;
                v = acc[mf][nf][0] + bias0; v = v>0.f?v:0.f; s0 += la*v;
                v = acc[mf][nf][1] + bias1; v = v>0.f?v:0.f; s1 += la*v;
                v = acc[mf][nf][2] + bias0; v = v>0.f?v:0.f; s0 += lb*v;
                v = acc[mf][nf][3] + bias1; v = v>0.f?v:0.f; s1 += lb*v;
            }
            cs[nf][0] = s0; cs[nf][1] = s1;
        }
        // fold the 8 lanes (stride 4) holding the same columns
        #pragma unroll
        for (int nf = 0; nf < 4; nf++){
            #pragma unroll
            for (int c = 0; c < 2; c++){
                float v = cs[nf][c];
                v += __shfl_down_sync(0xffffffffu, v, 4);
                v += __shfl_down_sync(0xffffffffu, v, 8);
                v += __shfl_down_sync(0xffffffffu, v, 16);
                cs[nf][c] = v;
            }
        }
        if (lane < 4){
            #pragma unroll
            for (int nf = 0; nf < 4; nf++){
                red2[warpRow][warpCol*32 + nf*8 + lane*2 + 0] = cs[nf][0];
                red2[warpRow][warpCol*32 + nf*8 + lane*2 + 1] = cs[nf][1];
            }
        }
    }
    __syncthreads();
    if (tid < 128)
        d_gpart[b][rt][ct*128 + tid] = red2[0][tid] + red2[1][tid];

    if (ct == 0 && tid == 0){
        float s = 0.f;
        #pragma unroll 8
        for (int i = 0; i < 128; i++) s += lab_s[i];
        d_lpart[b][rt] = s;
    }
}

// ============================================================================
// Stage 2: reduce gpart -> g; xt = (g@k1_w1)/M + b1*Lsum/M; m1 MLP + skip;
// logits_full = xt2 @ l1_w + l1_b; add gumbel to first 2048; store msg.
// ============================================================================
__global__ void __launch_bounds__(512) stage2_kernel(
    const float* __restrict__ k1w1, const float* __restrict__ k1b1,
    const float* __restrict__ m1w0, const float* __restrict__ m1b0,
    const float* __restrict__ m1w1, const float* __restrict__ m1b1,
    const float* __restrict__ l1w,  const float* __restrict__ l1b,
    const float* __restrict__ u)
{
    const int b = blockIdx.x;
    const int j = threadIdx.x;
    __shared__ float s0[HH], s1[HH];
    __shared__ float sL;

    float g = 0.f;
    #pragma unroll
    for (int rt=0;rt<16;rt++) g += d_gpart[b][rt][j];
    s0[j] = g;
    if (j == 0){
        float L = 0.f;
        #pragma unroll
        for (int rt=0;rt<16;rt++) L += d_lpart[b][rt];
        sL = L;
        d_Lsum[b] = L;
    }
    __syncthreads();
    const float Ls = sL;

    float acc = 0.f;
    #pragma unroll 4
    for (int k=0;k<HH;k++) acc += s0[k]*k1w1[k*HH + j];
    float xt = acc*INVM + k1b1[j]*(Ls*INVM);
    __syncthreads();
    s1[j] = xt;
    __syncthreads();

    acc = 0.f;
    #pragma unroll 4
    for (int k=0;k<HH;k++) acc += s1[k]*m1w0[k*HH + j];
    float t = fmaxf(acc + m1b0[j], 0.f);
    __syncthreads();
    s0[j] = t;
    __syncthreads();

    acc = 0.f;
    #pragma unroll 4
    for (int k=0;k<HH;k++) acc += s0[k]*m1w1[k*HH + j];
    float x2 = acc + m1b1[j] + xt;
    __syncthreads();
    s1[j] = x2;
    __syncthreads();

    for (int jj=j; jj<HH+MM; jj+=HH){
        float a2 = 0.f;
        #pragma unroll 4
        for (int k=0;k<HH;k++) a2 += s1[k]*l1w[(size_t)k*(HH+MM) + jj];
        a2 += l1b[jj];
        if (jj < MM){
            float uu = u[(size_t)b*MM + jj];
            a2 += -logf(-logf(uu));          // gumbel
            d_logits[b][jj] = a2;
        } else {
            d_msg[b][jj-MM] = a2;
        }
    }
}

// ============================================================================
// Stage 2b: per-batch top-K (K=64) iterative argmax (ties -> lowest index).
// ============================================================================
__global__ void __launch_bounds__(256) topk_kernel(const float* __restrict__ x)
{
    const int b = blockIdx.x;
    const int tid = threadIdx.x;
    __shared__ float v[MM];
    __shared__ float bv[256];
    __shared__ int   bi[256];

    for (int i=tid;i<MM;i+=256) v[i] = d_logits[b][i];
    __syncthreads();

    for (int sel=0; sel<KK; sel++){
        float best = -3.0e38f; int besti = MM;
        for (int i=tid;i<MM;i+=256){
            float val = v[i];
            if (val > best){ best = val; besti = i; }
        }
        bv[tid] = best; bi[tid] = besti;
        __syncthreads();
        for (int s=128;s>0;s>>=1){
            if (tid < s){
                float o = bv[tid+s]; int oi = bi[tid+s];
                if (o > bv[tid] || (o == bv[tid] && oi < bi[tid])){
                    bv[tid] = o; bi[tid] = oi;
                }
            }
            __syncthreads();
        }
        int w = bi[0];
        if (tid == 0){
            d_selIdx[b][sel] = w;
            v[w] = -3.0e38f;
        }
        __syncthreads();
    }

    float s = 0.f;
    if (tid < KK){
        int r = d_selIdx[b][tid];
        s = x[((size_t)b*MM + r)*XROW + DD];
    }
    bv[tid] = s;
    __syncthreads();
    for (int st=128; st>0; st>>=1){
        if (tid < st) bv[tid] += bv[tid+st];
        __syncthreads();
    }
    if (tid == 0) d_selLab[b] = bv[0];
}

// ============================================================================
// Stage 3: gathered tiled GEMM over the 64 selected rows. Grid (4, 64).
// ============================================================================
__global__ void __launch_bounds__(256) stage3_kernel(
    const float* __restrict__ x, const float* __restrict__ w0,
    const float* __restrict__ b0)
{
    const int ct = blockIdx.x;
    const int b  = blockIdx.y;
    const int tid = threadIdx.x;
    const int tx = tid & 15;
    const int ty = tid >> 4;

    __shared__ float As[2][16][68];
    __shared__ float Bs[2][16][128];
    __shared__ float red[16][128];
    __shared__ int   sidx[KK];
    __shared__ float lab[KK];

    if (tid < KK){
        int r = d_selIdx[b][tid];
        sidx[tid] = r;
        lab[tid] = x[((size_t)b*MM + r)*XROW + DD];
    }
    __syncthreads();

    const float* __restrict__ xb  = x + (size_t)b*MM*XROW;
    const float* __restrict__ w0c = w0 + ct*128;

    float acc[4][8];
    #pragma unroll
    for (int i=0;i<4;i++)
        #pragma unroll
        for (int j=0;j<8;j++) acc[i][j]=0.f;

    #pragma unroll
    for (int t=0;t<4;t++){
        int idx = tid + t*256;
        int row = idx >> 4, kk = idx & 15;
        As[0][kk][row] = xb[(size_t)sidx[row]*XROW + kk];
    }
    #pragma unroll
    for (int t=0;t<2;t++){
        int idx = tid + t*256;
        int kk = idx >> 5, colq = idx & 31;
        float4 v = *reinterpret_cast<const float4*>(&w0c[(size_t)kk*HH + colq*4]);
        *reinterpret_cast<float4*>(&Bs[0][kk][colq*4]) = v;
    }
    __syncthreads();

    int buf = 0;
    for (int k0=0;k0<DD;k0+=16){
        if (k0 + 16 < DD){
            int kn = k0 + 16;
            #pragma unroll
            for (int t=0;t<4;t++){
                int idx = tid + t*256;
                int row = idx >> 4, kk = idx & 15;
                As[buf^1][kk][row] = xb[(size_t)sidx[row]*XROW + kn + kk];
            }
            #pragma unroll
            for (int t=0;t<2;t++){
                int idx = tid + t*256;
                int kk = idx >> 5, colq = idx & 31;
                float4 v = *reinterpret_cast<const float4*>(&w0c[(size_t)(kn+kk)*HH + colq*4]);
                *reinterpret_cast<float4*>(&Bs[buf^1][kk][colq*4]) = v;
            }
        }
        #pragma unroll
        for (int kk=0;kk<16;kk++){
            float a[4], bw[8];
            #pragma unroll
            for (int i=0;i<4;i++) a[i]  = As[buf][kk][ty*4+i];
            #pragma unroll
            for (int j=0;j<8;j++) bw[j] = Bs[buf][kk][tx*8+j];
            #pragma unroll
            for (int i=0;i<4;i++)
                #pragma unroll
                for (int j=0;j<8;j++) acc[i][j] += a[i]*bw[j];
        }
        __syncthreads();
        buf ^= 1;
    }

    float lf[4];
    #pragma unroll
    for (int i=0;i<4;i++) lf[i] = lab[ty*4+i];
    float gf[8];
    #pragma unroll
    for (int j=0;j<8;j++){
        float bias = b0[ct*128 + tx*8 + j];
        float s = 0.f;
        #pragma unroll
        for (int i=0;i<4;i++){
            float v = acc[i][j] + bias;
            v = v > 0.f ? v : 0.f;
            s += lf[i]*v;
        }
        gf[j] = s;
    }
    #pragma unroll
    for (int j=0;j<8;j++) red[ty][tx*8+j] = gf[j];
    __syncthreads();
    if (tid < 128){
        float s = 0.f;
        #pragma unroll
        for (int t=0;t<16;t++) s += red[t][tid];
        d_g2[b][ct*128 + tid] = s;
    }
}

// ============================================================================
// Stage 4: final MLP chain -> out.
// ============================================================================
__global__ void __launch_bounds__(512) stage4_kernel(
    const float* __restrict__ k2w1, const float* __restrict__ k2b0,
    const float* __restrict__ k2b1,
    const float* __restrict__ m2w0, const float* __restrict__ m2b0,
    const float* __restrict__ m2w1, const float* __restrict__ m2b1,
    const float* __restrict__ l2w,  const float* __restrict__ l2b,
    float* __restrict__ out)
{
    const int b = blockIdx.x;
    const int j = threadIdx.x;
    __shared__ float g2s[HH];
    __shared__ float zs[2*HH];
    __shared__ float t1[HH];

    const float Ls = d_Lsum[b];
    const float un = Ls - d_selLab[b];
    g2s[j] = d_g2[b][j] + fmaxf(k2b0[j], 0.f)*un;
    __syncthreads();

    float acc = 0.f;
    #pragma unroll 4
    for (int k=0;k<HH;k++) acc += g2s[k]*k2w1[k*HH + j];
    float xt2 = (acc + k2b1[j]*Ls)*INVM;

    zs[j]      = xt2;
    zs[HH + j] = d_msg[b][j];
    __syncthreads();

    acc = 0.f;
    #pragma unroll 4
    for (int k=0;k<2*HH;k++) acc += zs[k]*m2w0[(size_t)k*HH + j];
    t1[j] = fmaxf(acc + m2b0[j], 0.f);
    __syncthreads();

    float y0 = 0.f, y1 = 0.f;
    #pragma unroll 4
    for (int k=0;k<HH;k++){
        float t = t1[k];
        y0 += t*m2w1[(size_t)k*(2*HH) + j];
        y1 += t*m2w1[(size_t)k*(2*HH) + j + HH];
    }
    y0 = fmaxf(y0 + m2b1[j],      0.f) + zs[j];
    y1 = fmaxf(y1 + m2b1[j + HH], 0.f) + zs[HH + j];
    __syncthreads();
    zs[j]      = y0;
    zs[HH + j] = y1;
    __syncthreads();

    acc = 0.f;
    #pragma unroll 4
    for (int k=0;k<2*HH;k++) acc += zs[k]*l2w[(size_t)k*OUTD + j];
    out[(size_t)b*OUTD + j] = acc + l2b[j];
}

// ============================================================================
extern "C" void kernel_launch(void* const* d_in, const int* in_sizes, int n_in,
                              void* d_out, int out_size)
{
    const float* x     = (const float*)d_in[0];
    const float* u     = (const float*)d_in[1];
    const float* k1w0  = (const float*)d_in[2];
    const float* k1b0  = (const float*)d_in[3];
    const float* k1w1  = (const float*)d_in[4];
    const float* k1b1  = (const float*)d_in[5];
    const float* k2w0  = (const float*)d_in[6];
    const float* k2b0  = (const float*)d_in[7];
    const float* k2w1  = (const float*)d_in[8];
    const float* k2b1  = (const float*)d_in[9];
    const float* m1w0  = (const float*)d_in[10];
    const float* m1b0  = (const float*)d_in[11];
    const float* m1w1  = (const float*)d_in[12];
    const float* m1b1  = (const float*)d_in[13];
    const float* m2w0  = (const float*)d_in[14];
    const float* m2b0  = (const float*)d_in[15];
    const float* m2w1  = (const float*)d_in[16];
    const float* m2b1  = (const float*)d_in[17];
    const float* l1w   = (const float*)d_in[18];
    const float* l1b   = (const float*)d_in[19];
    const float* l2w   = (const float*)d_in[20];
    const float* l2b   = (const float*)d_in[21];
    float* out = (float*)d_out;

    prep_w0_kernel<<<256, 512>>>(k1w0);
    dim3 g1(4, 16, BB);
    stage1_mma_kernel<<<g1, 256>>>(x, k1b0);
    stage2_kernel<<<BB, 512>>>(k1w1, k1b1, m1w0, m1b0, m1w1, m1b1, l1w, l1b, u);
    topk_kernel<<<BB, 256>>>(x);
    dim3 g3(4, BB);
    stage3_kernel<<<g3, 256>>>(x, k2w0, k2b0);
    stage4_kernel<<<BB, 512>>>(k2w1, k2b0, k2b1, m2w0, m2b0, m2w1, m2b1,
                               l2w, l2b, out);
}

// round 6
// speedup vs baseline: 1.7353x; 1.0010x over previous
#include <cuda_runtime.h>
#include <cuda_bf16.h>
#include <math.h>
#include <stdint.h>

// Problem constants
#define BB   64
#define MM   2048
#define DD   256
#define KK   64
#define HH   512
#define XROW 257          // x row = 256 feats + 1 label
#define OUTD 512
#define INVM (1.0f/2048.0f)

// ---------------- scratch (device globals; no allocation) ----------------
__device__ float d_gpart[BB][16][HH];   // stage1 partials per row-tile
__device__ float d_lpart[BB][16];       // label-sum partials
__device__ float d_Lsum[BB];
__device__ float d_logits[BB][MM];      // logits + gumbel
__device__ float d_msg[BB][HH];
__device__ int   d_selIdx[BB][KK];
__device__ float d_selLab[BB];
__device__ float d_g2[BB][HH];
// k1_w0 transposed to [n][k] bf16 hi/lo for ldmatrix-friendly B tiles
__device__ __nv_bfloat16 d_bthi[HH*DD];
__device__ __nv_bfloat16 d_btlo[HH*DD];

// ---------------- mma.sync helpers ----------------
#define LDSM4(R, addr) \
  asm volatile("ldmatrix.sync.aligned.m8n8.x4.shared.b16 {%0,%1,%2,%3}, [%4];" \
    : "=r"((R)[0]), "=r"((R)[1]), "=r"((R)[2]), "=r"((R)[3]) : "r"(addr))

#define MMA16816(C, A, B0v, B1v) \
  asm volatile("mma.sync.aligned.m16n8k16.row.col.f32.bf16.bf16.f32 " \
    "{%0,%1,%2,%3}, {%4,%5,%6,%7}, {%8,%9}, {%0,%1,%2,%3};" \
    : "+f"((C)[0]), "+f"((C)[1]), "+f"((C)[2]), "+f"((C)[3]) \
    : "r"((A)[0]), "r"((A)[1]), "r"((A)[2]), "r"((A)[3]), "r"(B0v), "r"(B1v))

__device__ __forceinline__ uint32_t smem_addr(const void* p){
    return (uint32_t)__cvta_generic_to_shared(p);
}

// ============================================================================
// Prep: transpose k1_w0 (fp32 [k=256][n=512]) -> bf16 hi/lo [n=512][k=256]
// ============================================================================
__global__ void __launch_bounds__(512) prep_w0_kernel(const float* __restrict__ w0)
{
    int id = blockIdx.x*512 + threadIdx.x;   // 0..131071
    int k  = id >> 9;                        // 0..255
    int n  = id & 511;                       // 0..511
    float v = w0[(size_t)k*HH + n];
    __nv_bfloat16 h = __float2bfloat16(v);
    __nv_bfloat16 l = __float2bfloat16(v - __bfloat162float(h));
    d_bthi[(size_t)n*DD + k] = h;
    d_btlo[(size_t)n*DD + k] = l;
}

// ============================================================================
// Stage 1 (mma.sync bf16 3-term split): per CTA computes
//   D[128 rows][128 cols] = feats(128x256) @ k1_w0[:, ct*128:+128]
// with fp32 accum via hi*hi + hi*lo + lo*hi, then fused bias+relu+
// label-weight epilogue reduced over rows -> d_gpart[b][rt][cols].
// Grid: (ct=4, rt=16, b=64) = 4096 CTAs, 256 threads (8 warps, 2x4 grid,
// warp tile 64x32). K chunks of 32 (2 k-steps of 16), single buffer.
// ============================================================================
__global__ void __launch_bounds__(256) stage1_mma_kernel(
    const float* __restrict__ x, const float* __restrict__ b0)
{
    const int ct = blockIdx.x;   // 0..3
    const int rt = blockIdx.y;   // 0..15
    const int b  = blockIdx.z;
    const int tid  = threadIdx.x;
    const int lane = tid & 31, wid = tid >> 5;
    const int warpRow = wid & 1;      // 2 row strips of 64
    const int warpCol = wid >> 1;     // 4 col strips of 32

    __shared__ __nv_bfloat16 Ah[128][40], Al[128][40];
    __shared__ __nv_bfloat16 Bh[128][40], Bl[128][40];
    __shared__ float lab_s[128];
    __shared__ float red2[2][128];

    const float* __restrict__ xb = x + (size_t)(b*MM + rt*128)*XROW;
    if (tid < 128) lab_s[tid] = xb[(size_t)tid*XROW + DD];

    float acc[4][4][4];               // [mf][nf][c]
    #pragma unroll
    for (int i=0;i<4;i++)
        #pragma unroll
        for (int j=0;j<4;j++)
            #pragma unroll
            for (int c=0;c<4;c++) acc[i][j][c] = 0.f;

    const __nv_bfloat16* __restrict__ bth = d_bthi + (size_t)(ct*128)*DD;
    const __nv_bfloat16* __restrict__ btl = d_btlo + (size_t)(ct*128)*DD;

    for (int kc = 0; kc < 8; kc++){
        __syncthreads();              // prior fragments consumed
        // ---- A: load fp32, convert to bf16 hi/lo ----
        {
            const int k = lane;       // 0..31
            #pragma unroll
            for (int it = 0; it < 16; it++){
                int row = (tid >> 5) + it*8;
                float v = xb[(size_t)row*XROW + kc*32 + k];
                __nv_bfloat16 h = __float2bfloat16(v);
                Ah[row][k] = h;
                Al[row][k] = __float2bfloat16(v - __bfloat162float(h));
            }
        }
        // ---- B: copy pre-transposed bf16 hi/lo rows (n-major) ----
        {
            int n  = tid >> 1;
            int j0 = (tid & 1)*2;
            const uint4* sh = reinterpret_cast<const uint4*>(bth + (size_t)n*DD + kc*32);
            const uint4* sl = reinterpret_cast<const uint4*>(btl + (size_t)n*DD + kc*32);
            uint4* dh = reinterpret_cast<uint4*>(&Bh[n][0]);
            uint4* dl = reinterpret_cast<uint4*>(&Bl[n][0]);
            dh[j0]   = sh[j0];
            dh[j0+1] = sh[j0+1];
            dl[j0]   = sl[j0];
            dl[j0+1] = sl[j0+1];
        }
        __syncthreads();

        #pragma unroll
        for (int ks = 0; ks < 2; ks++){
            uint32_t ah[4][4], al[4][4], bh[2][4], bl[2][4];
            const int arow = warpRow*64 + (lane & 15);
            const int acol = ks*16 + (lane >> 4)*8;
            #pragma unroll
            for (int mf = 0; mf < 4; mf++){
                LDSM4(ah[mf], smem_addr(&Ah[arow + mf*16][acol]));
                LDSM4(al[mf], smem_addr(&Al[arow + mf*16][acol]));
            }
            const int brow = warpCol*32 + (lane & 15);
            #pragma unroll
            for (int np = 0; np < 2; np++){
                LDSM4(bh[np], smem_addr(&Bh[brow + np*16][acol]));
                LDSM4(bl[np], smem_addr(&Bl[brow + np*16][acol]));
            }
            #pragma unroll
            for (int mf = 0; mf < 4; mf++){
                #pragma unroll
                for (int nf = 0; nf < 4; nf++){
                    const int np = nf >> 1, odd = nf & 1;
                    uint32_t b0h = bh[np][odd], b1h = bh[np][odd+2];
                    uint32_t b0l = bl[np][odd], b1l = bl[np][odd+2];
                    MMA16816(acc[mf][nf], ah[mf], b0h, b1h);
                    MMA16816(acc[mf][nf], ah[mf], b0l, b1l);
                    MMA16816(acc[mf][nf], al[mf], b0h, b1h);
                }
            }
        }
    }

    // ---- epilogue: bias + relu + label weight, reduce over 128 rows ----
    // thread owns (row0 = warpRow*64 + mf*16 + lane>>2, row1 = row0+8),
    // cols = warpCol*32 + nf*8 + (lane&3)*2 + {0,1}
    {
        const int r0 = warpRow*64 + (lane >> 2);
        float cs[4][2];
        #pragma unroll
        for (int nf = 0; nf < 4; nf++){
            const int colg = ct*128 + warpCol*32 + nf*8 + (lane & 3)*2;
            float bias0 = __ldg(&b0[colg]);
            float bias1 = __ldg(&b0[colg+1]);
            float s0 = 0.f, s1 = 0.f;
            #pragma unroll
            for (int mf = 0; mf < 4; mf++){
                float la = lab_s[r0 + mf*16];
                float lb = lab_s[r0 + mf*16 + 8];
                float v;
                v = acc[mf][nf][0] + bias0; v = v>0.f?v:0.f; s0 += la*v;
                v = acc[mf][nf][1] + bias1; v = v>0.f?v:0.f; s1 += la*v;
                v = acc[mf][nf][2] + bias0; v = v>0.f?v:0.f; s0 += lb*v;
                v = acc[mf][nf][3] + bias1; v = v>0.f?v:0.f; s1 += lb*v;
            }
            cs[nf][0] = s0; cs[nf][1] = s1;
        }
        // fold the 8 lanes (stride 4) holding the same columns
        #pragma unroll
        for (int nf = 0; nf < 4; nf++){
            #pragma unroll
            for (int c = 0; c < 2; c++){
                float v = cs[nf][c];
                v += __shfl_down_sync(0xffffffffu, v, 4);
                v += __shfl_down_sync(0xffffffffu, v, 8);
                v += __shfl_down_sync(0xffffffffu, v, 16);
                cs[nf][c] = v;
            }
        }
        if (lane < 4){
            #pragma unroll
            for (int nf = 0; nf < 4; nf++){
                red2[warpRow][warpCol*32 + nf*8 + lane*2 + 0] = cs[nf][0];
                red2[warpRow][warpCol*32 + nf*8 + lane*2 + 1] = cs[nf][1];
            }
        }
    }
    __syncthreads();
    if (tid < 128)
        d_gpart[b][rt][ct*128 + tid] = red2[0][tid] + red2[1][tid];

    if (ct == 0 && tid == 0){
        float s = 0.f;
        #pragma unroll 8
        for (int i = 0; i < 128; i++) s += lab_s[i];
        d_lpart[b][rt] = s;
    }
}

// ============================================================================
// Stage 2: reduce gpart -> g; xt = (g@k1_w1)/M + b1*Lsum/M; m1 MLP + skip;
// logits_full = xt2 @ l1_w + l1_b; add gumbel to first 2048; store msg.
// ============================================================================
__global__ void __launch_bounds__(512) stage2_kernel(
    const float* __restrict__ k1w1, const float* __restrict__ k1b1,
    const float* __restrict__ m1w0, const float* __restrict__ m1b0,
    const float* __restrict__ m1w1, const float* __restrict__ m1b1,
    const float* __restrict__ l1w,  const float* __restrict__ l1b,
    const float* __restrict__ u)
{
    const int b = blockIdx.x;
    const int j = threadIdx.x;
    __shared__ float s0[HH], s1[HH];
    __shared__ float sL;

    float g = 0.f;
    #pragma unroll
    for (int rt=0;rt<16;rt++) g += d_gpart[b][rt][j];
    s0[j] = g;
    if (j == 0){
        float L = 0.f;
        #pragma unroll
        for (int rt=0;rt<16;rt++) L += d_lpart[b][rt];
        sL = L;
        d_Lsum[b] = L;
    }
    __syncthreads();
    const float Ls = sL;

    float acc = 0.f;
    #pragma unroll 4
    for (int k=0;k<HH;k++) acc += s0[k]*k1w1[k*HH + j];
    float xt = acc*INVM + k1b1[j]*(Ls*INVM);
    __syncthreads();
    s1[j] = xt;
    __syncthreads();

    acc = 0.f;
    #pragma unroll 4
    for (int k=0;k<HH;k++) acc += s1[k]*m1w0[k*HH + j];
    float t = fmaxf(acc + m1b0[j], 0.f);
    __syncthreads();
    s0[j] = t;
    __syncthreads();

    acc = 0.f;
    #pragma unroll 4
    for (int k=0;k<HH;k++) acc += s0[k]*m1w1[k*HH + j];
    float x2 = acc + m1b1[j] + xt;
    __syncthreads();
    s1[j] = x2;
    __syncthreads();

    for (int jj=j; jj<HH+MM; jj+=HH){
        float a2 = 0.f;
        #pragma unroll 4
        for (int k=0;k<HH;k++) a2 += s1[k]*l1w[(size_t)k*(HH+MM) + jj];
        a2 += l1b[jj];
        if (jj < MM){
            float uu = u[(size_t)b*MM + jj];
            a2 += -logf(-logf(uu));          // gumbel
            d_logits[b][jj] = a2;
        } else {
            d_msg[b][jj-MM] = a2;
        }
    }
}

// ============================================================================
// Stage 2b: per-batch top-K (K=64) iterative argmax (ties -> lowest index).
// ============================================================================
__global__ void __launch_bounds__(256) topk_kernel(const float* __restrict__ x)
{
    const int b = blockIdx.x;
    const int tid = threadIdx.x;
    __shared__ float v[MM];
    __shared__ float bv[256];
    __shared__ int   bi[256];

    for (int i=tid;i<MM;i+=256) v[i] = d_logits[b][i];
    __syncthreads();

    for (int sel=0; sel<KK; sel++){
        float best = -3.0e38f; int besti = MM;
        for (int i=tid;i<MM;i+=256){
            float val = v[i];
            if (val > best){ best = val; besti = i; }
        }
        bv[tid] = best; bi[tid] = besti;
        __syncthreads();
        for (int s=128;s>0;s>>=1){
            if (tid < s){
                float o = bv[tid+s]; int oi = bi[tid+s];
                if (o > bv[tid] || (o == bv[tid] && oi < bi[tid])){
                    bv[tid] = o; bi[tid] = oi;
                }
            }
            __syncthreads();
        }
        int w = bi[0];
        if (tid == 0){
            d_selIdx[b][sel] = w;
            v[w] = -3.0e38f;
        }
        __syncthreads();
    }

    float s = 0.f;
    if (tid < KK){
        int r = d_selIdx[b][tid];
        s = x[((size_t)b*MM + r)*XROW + DD];
    }
    bv[tid] = s;
    __syncthreads();
    for (int st=128; st>0; st>>=1){
        if (tid < st) bv[tid] += bv[tid+st];
        __syncthreads();
    }
    if (tid == 0) d_selLab[b] = bv[0];
}

// ============================================================================
// Stage 3: gathered tiled GEMM over the 64 selected rows. Grid (4, 64).
// ============================================================================
__global__ void __launch_bounds__(256) stage3_kernel(
    const float* __restrict__ x, const float* __restrict__ w0,
    const float* __restrict__ b0)
{
    const int ct = blockIdx.x;
    const int b  = blockIdx.y;
    const int tid = threadIdx.x;
    const int tx = tid & 15;
    const int ty = tid >> 4;

    __shared__ float As[2][16][68];
    __shared__ float Bs[2][16][128];
    __shared__ float red[16][128];
    __shared__ int   sidx[KK];
    __shared__ float lab[KK];

    if (tid < KK){
        int r = d_selIdx[b][tid];
        sidx[tid] = r;
        lab[tid] = x[((size_t)b*MM + r)*XROW + DD];
    }
    __syncthreads();

    const float* __restrict__ xb  = x + (size_t)b*MM*XROW;
    const float* __restrict__ w0c = w0 + ct*128;

    float acc[4][8];
    #pragma unroll
    for (int i=0;i<4;i++)
        #pragma unroll
        for (int j=0;j<8;j++) acc[i][j]=0.f;

    #pragma unroll
    for (int t=0;t<4;t++){
        int idx = tid + t*256;
        int row = idx >> 4, kk = idx & 15;
        As[0][kk][row] = xb[(size_t)sidx[row]*XROW + kk];
    }
    #pragma unroll
    for (int t=0;t<2;t++){
        int idx = tid + t*256;
        int kk = idx >> 5, colq = idx & 31;
        float4 v = *reinterpret_cast<const float4*>(&w0c[(size_t)kk*HH + colq*4]);
        *reinterpret_cast<float4*>(&Bs[0][kk][colq*4]) = v;
    }
    __syncthreads();

    int buf = 0;
    for (int k0=0;k0<DD;k0+=16){
        if (k0 + 16 < DD){
            int kn = k0 + 16;
            #pragma unroll
            for (int t=0;t<4;t++){
                int idx = tid + t*256;
                int row = idx >> 4, kk = idx & 15;
                As[buf^1][kk][row] = xb[(size_t)sidx[row]*XROW + kn + kk];
            }
            #pragma unroll
            for (int t=0;t<2;t++){
                int idx = tid + t*256;
                int kk = idx >> 5, colq = idx & 31;
                float4 v = *reinterpret_cast<const float4*>(&w0c[(size_t)(kn+kk)*HH + colq*4]);
                *reinterpret_cast<float4*>(&Bs[buf^1][kk][colq*4]) = v;
            }
        }
        #pragma unroll
        for (int kk=0;kk<16;kk++){
            float a[4], bw[8];
            #pragma unroll
            for (int i=0;i<4;i++) a[i]  = As[buf][kk][ty*4+i];
            #pragma unroll
            for (int j=0;j<8;j++) bw[j] = Bs[buf][kk][tx*8+j];
            #pragma unroll
            for (int i=0;i<4;i++)
                #pragma unroll
                for (int j=0;j<8;j++) acc[i][j] += a[i]*bw[j];
        }
        __syncthreads();
        buf ^= 1;
    }

    float lf[4];
    #pragma unroll
    for (int i=0;i<4;i++) lf[i] = lab[ty*4+i];
    float gf[8];
    #pragma unroll
    for (int j=0;j<8;j++){
        float bias = b0[ct*128 + tx*8 + j];
        float s = 0.f;
        #pragma unroll
        for (int i=0;i<4;i++){
            float v = acc[i][j] + bias;
            v = v > 0.f ? v : 0.f;
            s += lf[i]*v;
        }
        gf[j] = s;
    }
    #pragma unroll
    for (int j=0;j<8;j++) red[ty][tx*8+j] = gf[j];
    __syncthreads();
    if (tid < 128){
        float s = 0.f;
        #pragma unroll
        for (int t=0;t<16;t++) s += red[t][tid];
        d_g2[b][ct*128 + tid] = s;
    }
}

// ============================================================================
// Stage 4: final MLP chain -> out.
// ============================================================================
__global__ void __launch_bounds__(512) stage4_kernel(
    const float* __restrict__ k2w1, const float* __restrict__ k2b0,
    const float* __restrict__ k2b1,
    const float* __restrict__ m2w0, const float* __restrict__ m2b0,
    const float* __restrict__ m2w1, const float* __restrict__ m2b1,
    const float* __restrict__ l2w,  const float* __restrict__ l2b,
    float* __restrict__ out)
{
    const int b = blockIdx.x;
    const int j = threadIdx.x;
    __shared__ float g2s[HH];
    __shared__ float zs[2*HH];
    __shared__ float t1[HH];

    const float Ls = d_Lsum[b];
    const float un = Ls - d_selLab[b];
    g2s[j] = d_g2[b][j] + fmaxf(k2b0[j], 0.f)*un;
    __syncthreads();

    float acc = 0.f;
    #pragma unroll 4
    for (int k=0;k<HH;k++) acc += g2s[k]*k2w1[k*HH + j];
    float xt2 = (acc + k2b1[j]*Ls)*INVM;

    zs[j]      = xt2;
    zs[HH + j] = d_msg[b][j];
    __syncthreads();

    acc = 0.f;
    #pragma unroll 4
    for (int k=0;k<2*HH;k++) acc += zs[k]*m2w0[(size_t)k*HH + j];
    t1[j] = fmaxf(acc + m2b0[j], 0.f);
    __syncthreads();

    float y0 = 0.f, y1 = 0.f;
    #pragma unroll 4
    for (int k=0;k<HH;k++){
        float t = t1[k];
        y0 += t*m2w1[(size_t)k*(2*HH) + j];
        y1 += t*m2w1[(size_t)k*(2*HH) + j + HH];
    }
    y0 = fmaxf(y0 + m2b1[j],      0.f) + zs[j];
    y1 = fmaxf(y1 + m2b1[j + HH], 0.f) + zs[HH + j];
    __syncthreads();
    zs[j]      = y0;
    zs[HH + j] = y1;
    __syncthreads();

    acc = 0.f;
    #pragma unroll 4
    for (int k=0;k<2*HH;k++) acc += zs[k]*l2w[(size_t)k*OUTD + j];
    out[(size_t)b*OUTD + j] = acc + l2b[j];
}

// ============================================================================
extern "C" void kernel_launch(void* const* d_in, const int* in_sizes, int n_in,
                              void* d_out, int out_size)
{
    const float* x     = (const float*)d_in[0];
    const float* u     = (const float*)d_in[1];
    const float* k1w0  = (const float*)d_in[2];
    const float* k1b0  = (const float*)d_in[3];
    const float* k1w1  = (const float*)d_in[4];
    const float* k1b1  = (const float*)d_in[5];
    const float* k2w0  = (const float*)d_in[6];
    const float* k2b0  = (const float*)d_in[7];
    const float* k2w1  = (const float*)d_in[8];
    const float* k2b1  = (const float*)d_in[9];
    const float* m1w0  = (const float*)d_in[10];
    const float* m1b0  = (const float*)d_in[11];
    const float* m1w1  = (const float*)d_in[12];
    const float* m1b1  = (const float*)d_in[13];
    const float* m2w0  = (const float*)d_in[14];
    const float* m2b0  = (const float*)d_in[15];
    const float* m2w1  = (const float*)d_in[16];
    const float* m2b1  = (const float*)d_in[17];
    const float* l1w   = (const float*)d_in[18];
    const float* l1b   = (const float*)d_in[19];
    const float* l2w   = (const float*)d_in[20];
    const float* l2b   = (const float*)d_in[21];
    float* out = (float*)d_out;

    prep_w0_kernel<<<256, 512>>>(k1w0);
    dim3 g1(4, 16, BB);
    stage1_mma_kernel<<<g1, 256>>>(x, k1b0);
    stage2_kernel<<<BB, 512>>>(k1w1, k1b1, m1w0, m1b0, m1w1, m1b1, l1w, l1b, u);
    topk_kernel<<<BB, 256>>>(x);
    dim3 g3(4, BB);
    stage3_kernel<<<g3, 256>>>(x, k2w0, k2b0);
    stage4_kernel<<<BB, 512>>>(k2w1, k2b0, k2b1, m2w0, m2b0, m2w1, m2b1,
                               l2w, l2b, out);
}